// round 14
// baseline (speedup 1.0000x reference)
#include <cuda_runtime.h>
#include <cstdint>
#include <climits>

#define BDIM 512
constexpr int Bn = 16, Nn = 2000, Hh = 512, Ww = 512, MAXD = 10, TOPK_ = 5;
constexpr float CONF = 0.2f, IOUT = 0.4f;
constexpr int KMAX = 256;
constexpr int RPB = 8;                     // render blocks per image
constexpr int RENB = Bn * RPB;             // 128
constexpr int GRID = Bn + RENB;            // 144 <= 148: one wave, all resident
constexpr unsigned FULL = 0xffffffffu;

// NMS -> render handshake (zero-init; reset by last render block each replay)
__device__ int g_flag[Bn];
__device__ int g_ib[Bn][MAXD][4];
__device__ int g_k[Bn][MAXD];
__device__ int g_done;

// IOU > IOUT  <=>  inter*(1+IOUT) > IOUT*(areaA+areaB+1e-9)   (denominator > 0)
__device__ __forceinline__ bool iou_gt(float ax1, float ay1, float ax2, float ay2, float aA,
                                       float bx1, float by1, float bx2, float by2, float aB) {
    float ix1 = fmaxf(ax1, bx1), iy1 = fmaxf(ay1, by1);
    float ix2 = fminf(ax2, bx2), iy2 = fminf(ay2, by2);
    float it = fmaxf(ix2 - ix1, 0.f) * fmaxf(iy2 - iy1, 0.f);
    return it * (1.0f + IOUT) > IOUT * (aA + aB + 1e-9f);
}

extern __shared__ unsigned char dynsmem[];
// layout: ckey ULL[2048] @0 (16K), sbox float4[2048] @16384 (32K),
//         ssc float[2048] @49152 (8K), sarea float[2048] @57344 (8K)
constexpr int SMEM_TOTAL = 65536;

__global__ __launch_bounds__(BDIM) void fused_kernel(const float* __restrict__ region,
                                                     const float* __restrict__ neg,
                                                     float* __restrict__ out,
                                                     float* __restrict__ out_tb,
                                                     float* __restrict__ out_k2) {
    const int t = threadIdx.x;
    const int lane = t & 31;

    // ================= render blocks: prefill rows, wait, fix covered =================
    if (blockIdx.x >= Bn) {
        const int rblk = blockIdx.x - Bn;
        const int img = rblk >> 3;
        const int r0 = (rblk & 7) * 64;          // this block owns rows [r0, r0+64)
        float* base = out + (size_t)img * Hh * Ww;
        float4* ob = (float4*)base + (size_t)r0 * (Ww / 4);
        float4 one = make_float4(1.f, 1.f, 1.f, 1.f);
#pragma unroll
        for (int i = 0; i < 16; i++) ob[t + i * BDIM] = one;    // 64 rows of 1.0f

        __shared__ int sx1[MAXD], sy1[MAXD], sx2[MAXD], sy2[MAXD], sk[MAXD];
        if (t == 0) {
            while (*(volatile int*)&g_flag[img] == 0) { __nanosleep(64); }
            __threadfence();
        }
        __syncthreads();
        if (t < MAXD) {
            sk[t] = g_k[img][t];
            sx1[t] = g_ib[img][t][0]; sy1[t] = g_ib[img][t][1];
            sx2[t] = g_ib[img][t][2]; sy2[t] = g_ib[img][t][3];
        }
        __syncthreads();
        const int wid = t >> 5;
        if (wid < MAXD && sk[wid]) {             // warp per box; boxes are <=21px wide
            int x1 = max(sx1[wid], 0), x2 = min(sx2[wid], Ww);
            int y1 = max(max(sy1[wid], r0), 0);
            int y2 = min(min(sy2[wid], r0 + 64), Hh);
            int w = x2 - x1;
            for (int y = y1; y < y2; y++)
                for (int xo = lane; xo < w; xo += 32)
                    base[y * Ww + x1 + xo] = 0.0f;
        }
        __syncthreads();
        if (t == 0) {
            int d = atomicAdd(&g_done, 1);
            if (d == RENB - 1) {                 // last render block resets handshake
                for (int i = 0; i < Bn; i++) g_flag[i] = 0;
                g_done = 0;
            }
        }
        return;
    }

    // ================= NMS blocks =================
    unsigned long long* ckey = (unsigned long long*)dynsmem;
    float4* sbox = (float4*)(dynsmem + 16384);
    float* ssc = (float*)(dynsmem + 49152);
    float* sarea = (float*)(dynsmem + 57344);

    __shared__ float sneg[MAXD * 5];
    __shared__ float okx1[MAXD], oky1[MAXD], okx2[MAXD], oky2[MAXD], oksc[MAXD];
    __shared__ float sxb[MAXD][5];
    __shared__ float4 skept[KMAX];
    __shared__ float skarea[KMAX];
    __shared__ unsigned s_sup[32];
    __shared__ float sconf0[MAXD];
    __shared__ int s_supb[MAXD];
    __shared__ unsigned int sh_maxbits;
    __shared__ int sh_cnt, sh_tot, sh_found;

    const int b = blockIdx.x;
    const float* rb = region + (size_t)b * Nn * 5;

    if (t == 0) { sh_maxbits = 0u; sh_tot = 0; }
    __syncthreads();

    // ---- pass 1: scores into registers + block max ----
    float rs[4];
    int rjx[4];
    int rn = 0;
    unsigned lm = 0u;
#pragma unroll
    for (int k = 0; k < 4; k++) {
        int j = t + k * BDIM;
        if (j < Nn) {
            float sc = __ldg(rb + j * 5 + 4);    // scores > 0
            rs[rn] = sc; rjx[rn] = j; rn++;
            lm = max(lm, __float_as_uint(sc));
        }
    }
#pragma unroll
    for (int off = 16; off; off >>= 1)
        lm = max(lm, __shfl_xor_sync(FULL, lm, off));
    if (lane == 0) atomicMax(&sh_maxbits, lm);
    if (t < MAXD * 5) sneg[t] = neg[(size_t)b * MAXD * 5 + t];
    __syncthreads();

    const float maxsc = __uint_as_float(sh_maxbits);
    const bool has_conf = maxsc > CONF;
    const float thresh = has_conf ? CONF : 0.0f;
    const int limit = has_conf ? MAXD : TOPK_;
    const float thrlv[3] = { maxsc - 0.03f, maxsc - 0.15f, -1.0f };

    // ---- escalating candidate selection (level 2 = all valid -> exact) ----
    for (int lev = 0; lev < 3; lev++) {
        if (t == 0) { sh_cnt = 0; sh_found = 0; }
        __syncthreads();
        const float thrL = thrlv[lev];
#pragma unroll
        for (int k = 0; k < 4; k++) {
            bool v = (k < rn) && (rs[k] > thresh);
            if (lev == 0) {
                unsigned bal = __ballot_sync(FULL, v);
                if (lane == 0) atomicAdd(&sh_tot, __popc(bal));
            }
            if (v && rs[k] > thrL) {
                int pos = atomicAdd(&sh_cnt, 1);
                ckey[pos] = ((unsigned long long)__float_as_uint(rs[k]) << 32) |
                            (unsigned)(Nn - 1 - rjx[k]);
            }
        }
        __syncthreads();
        const int C = sh_cnt;

        // rank sort (keys unique -> exact stable desc order) + gather boxes from L2
        for (int i = t; i < C; i += BDIM) {
            unsigned long long ki = ckey[i];
            int r = 0;
            for (int j = 0; j < C; j++) r += (ckey[j] > ki);
            int js = (Nn - 1) - (int)(unsigned)(ki & 0xffffffffu);
            const float* p = rb + js * 5;
            float x1 = __ldg(p), y1 = __ldg(p + 1), x2 = __ldg(p + 2), y2 = __ldg(p + 3);
            sbox[r] = make_float4(x1, y1, x2, y2);
            sarea[r] = fmaxf(x2 - x1, 0.f) * fmaxf(y2 - y1, 0.f);
            ssc[r] = __uint_as_float((unsigned)(ki >> 32));
        }
        __syncthreads();

        // ---- single-warp greedy NMS: parallel IOU matrix + ALU recurrence ----
        if (t < 32) {
            int nkept = 0, found = 0;
            bool stop = false;
            for (int c0 = 0; c0 < C && !stop; c0 += 32) {
                int ci = c0 + lane;
                bool valid = ci < C;
                float4 bb = valid ? sbox[ci] : make_float4(0.f, 0.f, 0.f, 0.f);
                float ar = valid ? sarea[ci] : 0.f;
                float sc = valid ? ssc[ci] : 0.f;
                bool alive = valid;
                for (int k = 0; k < nkept; k++) {
                    float4 kb = skept[k];
                    if (alive && iou_gt(kb.x, kb.y, kb.z, kb.w, skarea[k],
                                        bb.x, bb.y, bb.z, bb.w, ar))
                        alive = false;
                }
                unsigned sup = 0;
#pragma unroll 4
                for (int j = 0; j < 32; j++) {
                    if (j < lane && valid) {
                        float4 jb = sbox[c0 + j];
                        if (iou_gt(jb.x, jb.y, jb.z, jb.w, sarea[c0 + j],
                                   bb.x, bb.y, bb.z, bb.w, ar))
                            sup |= (1u << j);
                    }
                }
                s_sup[lane] = sup;
                unsigned alivem = __ballot_sync(FULL, alive);
                bool tiny = valid && (bb.z - bb.x >= 1.0f) && (bb.w - bb.y >= 1.0f);
                unsigned tinym = __ballot_sync(FULL, tiny);
                __syncwarp();
                unsigned kept = 0;
#pragma unroll 4
                for (int i = 0; i < 32; i++) {
                    if ((alivem >> i) & 1u) {
                        if ((s_sup[i] & kept) == 0u) kept |= (1u << i);
                    }
                }
                unsigned ktiny = kept & tinym;
                int cf = __popc(ktiny);
                if ((ktiny >> lane) & 1u) {
                    int r = found + __popc(ktiny & ((1u << lane) - 1u));
                    if (r < limit) {
                        okx1[r] = bb.x; oky1[r] = bb.y;
                        okx2[r] = bb.z; oky2[r] = bb.w;
                        oksc[r] = sc;
                    }
                }
                if (found + cf >= limit) {
                    found = limit;
                    stop = true;
                } else {
                    found += cf;
                    if ((kept >> lane) & 1u) {
                        int p = nkept + __popc(kept & ((1u << lane) - 1u));
                        if (p < KMAX) { skept[p] = bb; skarea[p] = ar; }
                    }
                    nkept += __popc(kept);
                    if (nkept >= KMAX) stop = true;
                }
                __syncwarp();
            }
            if (lane == 0) sh_found = found;
        }
        __syncthreads();

        if (sh_found >= limit || C >= sh_tot) break;
    }

    // ---- stage 2: warp-parallel 10-box merge + stable sort + bitmask NMS ----
    if (t < 32) {
        const int cnt = min(sh_found, limit);
        float bx[5];
        bx[0] = bx[1] = bx[2] = bx[3] = 0.f;
        bx[4] = -1.0f;
        if (lane < MAXD) {
            if (lane < cnt) {
                bx[0] = okx1[lane]; bx[1] = oky1[lane];
                bx[2] = okx2[lane]; bx[3] = oky2[lane];
                bx[4] = oksc[lane];
            } else {
#pragma unroll
                for (int c = 0; c < 5; c++) bx[c] = sneg[lane * 5 + c];
            }
            sconf0[lane] = bx[4];
        }
        __syncwarp();
        if (lane < MAXD) {
            int rank = 0;
#pragma unroll
            for (int j = 0; j < MAXD; j++) {
                float cj = sconf0[j];
                rank += (cj > bx[4]) || (cj == bx[4] && j < lane);
            }
#pragma unroll
            for (int c = 0; c < 5; c++) sxb[rank][c] = bx[c];
        }
        __syncwarp();
        if (lane < MAXD) {
#pragma unroll
            for (int c = 0; c < 5; c++) bx[c] = sxb[lane][c];
        }
        __syncwarp();
        unsigned supb = 0;
        if (lane < MAXD) {
            float aA = fmaxf(bx[2] - bx[0], 0.f) * fmaxf(bx[3] - bx[1], 0.f);
#pragma unroll
            for (int j = 0; j < MAXD; j++) {
                float jx1 = sxb[j][0], jy1 = sxb[j][1], jx2 = sxb[j][2], jy2 = sxb[j][3];
                float aJ = fmaxf(jx2 - jx1, 0.f) * fmaxf(jy2 - jy1, 0.f);
                if (iou_gt(jx1, jy1, jx2, jy2, aJ, bx[0], bx[1], bx[2], bx[3], aA))
                    supb |= (1u << j);
            }
            s_supb[lane] = (int)supb;
        }
        unsigned validm = __ballot_sync(FULL, lane < MAXD && bx[4] > 0.0f);
        __syncwarp();
        unsigned kept = 0;
#pragma unroll
        for (int i = 0; i < MAXD; i++) {
            if ((validm >> i) & 1u) {
                if (((unsigned)s_supb[i] & kept & ((1u << i) - 1u)) == 0u)
                    kept |= (1u << i);
            }
        }
        bool kp = (lane < MAXD) && ((kept >> lane) & 1u);
        if (lane < MAXD) {
#pragma unroll
            for (int c = 0; c < 4; c++) {
                out_tb[(size_t)b * MAXD * 4 + lane * 4 + c] = kp ? bx[c] : 0.0f;
                g_ib[b][lane][c] = (int)floorf(bx[c] + 0.5f);
            }
            out_k2[(size_t)b * MAXD + lane] = kp ? 1.0f : 0.0f;
            g_k[b][lane] = kp ? 1 : 0;
        }
    }
    __syncthreads();
    // publish: release flag so this image's render blocks can fix covered pixels
    if (t == 0) {
        __threadfence();
        *(volatile int*)&g_flag[b] = 1;
    }
}

extern "C" void kernel_launch(void* const* d_in, const int* in_sizes, int n_in,
                              void* d_out, int out_size) {
    // inputs: [0]=x (unused), [1]=region_boxes (B,N,5), [2]=neg_boxes (B,10,5)
    const float* region = (const float*)d_in[1];
    const float* neg = (const float*)d_in[2];
    float* out = (float*)d_out;
    float* out_tb = out + (size_t)Bn * Hh * Ww;          // target_boxes segment
    float* out_k2 = out_tb + (size_t)Bn * MAXD * 4;      // keep2 segment

    cudaFuncSetAttribute(fused_kernel, cudaFuncAttributeMaxDynamicSharedMemorySize, SMEM_TOTAL);
    fused_kernel<<<GRID, BDIM, SMEM_TOTAL>>>(region, neg, out, out_tb, out_k2);
}

// round 15
// speedup vs baseline: 1.0333x; 1.0333x over previous
#include <cuda_runtime.h>
#include <cstdint>
#include <climits>

#define BDIM 512
constexpr int Bn = 16, Nn = 2000, Hh = 512, Ww = 512, MAXD = 10, TOPK_ = 5;
constexpr float CONF = 0.2f, IOUT = 0.4f;
constexpr int KMAX = 256;
constexpr int FASTC = 128;                 // fast-path candidate cap
constexpr int RPB = 8;                     // render blocks per image
constexpr int RENB = Bn * RPB;             // 128
constexpr int GRID = Bn + RENB;            // 144 <= 148: one wave, all resident
constexpr unsigned FULL = 0xffffffffu;

// NMS -> render handshake (zero-init; reset by last render block each replay)
__device__ int g_flag[Bn];
__device__ int g_ib[Bn][MAXD][4];
__device__ int g_k[Bn][MAXD];
__device__ int g_done;

// IOU > IOUT  <=>  inter*(1+IOUT) > IOUT*(areaA+areaB+1e-9)
__device__ __forceinline__ bool iou_gt(float ax1, float ay1, float ax2, float ay2, float aA,
                                       float bx1, float by1, float bx2, float by2, float aB) {
    float ix1 = fmaxf(ax1, bx1), iy1 = fmaxf(ay1, by1);
    float ix2 = fminf(ax2, bx2), iy2 = fminf(ay2, by2);
    float it = fmaxf(ix2 - ix1, 0.f) * fmaxf(iy2 - iy1, 0.f);
    return it * (1.0f + IOUT) > IOUT * (aA + aB + 1e-9f);
}

extern __shared__ unsigned char dynsmem[];
// layout:
//   sdata : float[10240]   @ 0       (40960 B; staged region slice)
//   ckey  : ULL[2048]      @ 40960   (16384 B)
//   sbox  : float4[2048]   @ 57344   (32768 B)  sorted boxes
//   ssc   : float[2048]    @ 90112   (8192 B)   sorted scores
//   sarea : float[2048]    @ 98304   (8192 B)   sorted areas
constexpr int SMEM_TOTAL = 106496;

__global__ __launch_bounds__(BDIM) void fused_kernel(const float* __restrict__ region,
                                                     const float* __restrict__ neg,
                                                     float* __restrict__ out,
                                                     float* __restrict__ out_tb,
                                                     float* __restrict__ out_k2) {
    const int t = threadIdx.x;
    const int lane = t & 31;

    // ================= render blocks: prefill rows, wait, fix covered =================
    if (blockIdx.x >= Bn) {
        const int rblk = blockIdx.x - Bn;
        const int img = rblk >> 3;
        const int r0 = (rblk & 7) * 64;          // rows [r0, r0+64)
        float* base = out + (size_t)img * Hh * Ww;
        float4* ob = (float4*)base + (size_t)r0 * (Ww / 4);
        float4 one = make_float4(1.f, 1.f, 1.f, 1.f);
#pragma unroll
        for (int i = 0; i < 16; i++) ob[t + i * BDIM] = one;

        __shared__ int sx1[MAXD], sy1[MAXD], sx2[MAXD], sy2[MAXD], sk[MAXD];
        if (t == 0) {
            while (*(volatile int*)&g_flag[img] == 0) { __nanosleep(64); }
            __threadfence();
        }
        __syncthreads();
        if (t < MAXD) {
            sk[t] = g_k[img][t];
            sx1[t] = g_ib[img][t][0]; sy1[t] = g_ib[img][t][1];
            sx2[t] = g_ib[img][t][2]; sy2[t] = g_ib[img][t][3];
        }
        __syncthreads();
        const int wid = t >> 5;
        if (wid < MAXD && sk[wid]) {             // warp per box; boxes <=21px wide
            int x1 = max(sx1[wid], 0), x2 = min(sx2[wid], Ww);
            int y1 = max(max(sy1[wid], r0), 0);
            int y2 = min(min(sy2[wid], r0 + 64), Hh);
            int w = x2 - x1;
            for (int y = y1; y < y2; y++)
                for (int xo = lane; xo < w; xo += 32)
                    base[y * Ww + x1 + xo] = 0.0f;
        }
        __syncthreads();
        if (t == 0) {
            int d = atomicAdd(&g_done, 1);
            if (d == RENB - 1) {
                for (int i = 0; i < Bn; i++) g_flag[i] = 0;
                g_done = 0;
            }
        }
        return;
    }

    // ================= NMS blocks =================
    float* sdata = (float*)dynsmem;
    unsigned long long* ckey = (unsigned long long*)(dynsmem + 40960);
    float4* sbox = (float4*)(dynsmem + 57344);
    float* ssc = (float*)(dynsmem + 90112);
    float* sarea = (float*)(dynsmem + 98304);

    __shared__ float sneg[MAXD * 5];
    __shared__ float okx1[MAXD], oky1[MAXD], okx2[MAXD], oky2[MAXD], oksc[MAXD];
    __shared__ float sxb[MAXD][5];
    __shared__ float4 skept[KMAX];
    __shared__ float skarea[KMAX];
    __shared__ unsigned s_sup[32];
    __shared__ unsigned long long s_supA[FASTC], s_supB[FASTC];
    __shared__ unsigned char s_tf[FASTC];
    __shared__ int okidx[MAXD];
    __shared__ float sconf0[MAXD];
    __shared__ int s_supb[MAXD];
    __shared__ unsigned int sh_maxbits;
    __shared__ int sh_cnt, sh_cntA, sh_found;

    const int b = blockIdx.x;
    const float* rb = region + (size_t)b * Nn * 5;

    if (t == 0) { sh_maxbits = 0u; sh_cntA = 0; }
    __syncthreads();

    // ---- pass 1: coalesced stage of the full 40KB slice + neg ----
    {
        const float4* rb4 = (const float4*)rb;
        float4* s4 = (float4*)sdata;
#pragma unroll
        for (int k = 0; k < 5; k++) {
            int i = t + k * BDIM;
            if (i < Nn * 5 / 4) s4[i] = rb4[i];
        }
        if (t < MAXD * 5) sneg[t] = neg[(size_t)b * MAXD * 5 + t];
    }
    __syncthreads();

    // ---- pass 2: scores from smem -> max + count(sc > CONF) ----
    float rs[4];
    unsigned lm = 0u;
    int myA = 0;
#pragma unroll
    for (int k = 0; k < 4; k++) {
        int j = t + k * BDIM;
        float sc = (j < Nn) ? sdata[j * 5 + 4] : 0.0f;   // scores > 0
        rs[k] = sc;
        lm = max(lm, __float_as_uint(sc));
        myA += (sc > CONF);
    }
#pragma unroll
    for (int off = 16; off; off >>= 1) {
        lm = max(lm, __shfl_xor_sync(FULL, lm, off));
        myA += __shfl_xor_sync(FULL, myA, off);
    }
    if (lane == 0) { atomicMax(&sh_maxbits, lm); atomicAdd(&sh_cntA, myA); }
    __syncthreads();

    const float maxsc = __uint_as_float(sh_maxbits);
    const bool has_conf = maxsc > CONF;
    const float thresh = has_conf ? CONF : 0.0f;
    const int limit = has_conf ? MAXD : TOPK_;
    const int total_valid = has_conf ? sh_cntA : Nn;

    // ---- escalating selection: lev0 = top band (fast), lev1 = all valid (exact) ----
    for (int lev = 0; lev < 2; lev++) {
        if (t == 0) { sh_cnt = 0; sh_found = 0; }
        __syncthreads();
        const float thrL = (lev == 0) ? (maxsc - 0.02f) : -1.0f;
#pragma unroll
        for (int k = 0; k < 4; k++) {
            int j = t + k * BDIM;
            float sc = rs[k];
            if (j < Nn && sc > thresh && sc > thrL) {
                int pos = atomicAdd(&sh_cnt, 1);
                ckey[pos] = ((unsigned long long)__float_as_uint(sc) << 32) |
                            (unsigned)(Nn - 1 - j);
            }
        }
        __syncthreads();
        const int C = sh_cnt;

        // rank sort (keys unique -> exact stable desc order); boxes from smem
        for (int i = t; i < C; i += BDIM) {
            unsigned long long ki = ckey[i];
            int r = 0;
            for (int j = 0; j < C; j++) r += (ckey[j] > ki);
            int js = (Nn - 1) - (int)(unsigned)(ki & 0xffffffffu);
            float x1 = sdata[js * 5 + 0], y1 = sdata[js * 5 + 1];
            float x2 = sdata[js * 5 + 2], y2 = sdata[js * 5 + 3];
            sbox[r] = make_float4(x1, y1, x2, y2);
            sarea[r] = fmaxf(x2 - x1, 0.f) * fmaxf(y2 - y1, 0.f);
            ssc[r] = __uint_as_float((unsigned)(ki >> 32));
        }
        __syncthreads();

        if (C <= FASTC) {
            // ---- FAST PATH: parallel adjacency + tiny-flag, then greedy recurrence ----
            if (t < C) {
                float4 bb = sbox[t];
                float ar = sarea[t];
                unsigned long long a = 0ull, bm = 0ull;
                for (int j = 0; j < t; j++) {
                    float4 jb = sbox[j];
                    if (iou_gt(jb.x, jb.y, jb.z, jb.w, sarea[j],
                               bb.x, bb.y, bb.z, bb.w, ar)) {
                        if (j < 64) a |= 1ull << j;
                        else bm |= 1ull << (j - 64);
                    }
                }
                s_supA[t] = a; s_supB[t] = bm;
                s_tf[t] = ((bb.z - bb.x >= 1.0f) && (bb.w - bb.y >= 1.0f)) ? 1 : 0;
            }
            __syncthreads();
            if (t == 0) {
                unsigned long long keptA = 0ull, keptB = 0ull;
                int f = 0;
                for (int i = 0; i < C && f < limit; i++) {
                    bool sup = ((s_supA[i] & keptA) | (s_supB[i] & keptB)) != 0ull;
                    if (!sup) {
                        if (i < 64) keptA |= 1ull << i; else keptB |= 1ull << (i - 64);
                        if (s_tf[i]) okidx[f++] = i;
                    }
                }
                sh_found = f;
            }
            __syncthreads();
            if (t < sh_found) {            // t < limit <= 10: warp 0
                int r = okidx[t];
                float4 bb = sbox[r];
                okx1[t] = bb.x; oky1[t] = bb.y; okx2[t] = bb.z; oky2[t] = bb.w;
                oksc[t] = ssc[r];
            }
            __syncthreads();
        } else {
            // ---- FALLBACK: chunked single-warp greedy NMS (exact for any C) ----
            if (t < 32) {
                int nkept = 0, found = 0;
                bool stop = false;
                for (int c0 = 0; c0 < C && !stop; c0 += 32) {
                    int ci = c0 + lane;
                    bool valid = ci < C;
                    float4 bb = valid ? sbox[ci] : make_float4(0.f, 0.f, 0.f, 0.f);
                    float ar = valid ? sarea[ci] : 0.f;
                    float sc = valid ? ssc[ci] : 0.f;
                    bool alive = valid;
                    for (int k = 0; k < nkept; k++) {
                        float4 kb = skept[k];
                        if (alive && iou_gt(kb.x, kb.y, kb.z, kb.w, skarea[k],
                                            bb.x, bb.y, bb.z, bb.w, ar))
                            alive = false;
                    }
                    unsigned sup = 0;
#pragma unroll 4
                    for (int j = 0; j < 32; j++) {
                        if (j < lane && valid) {
                            float4 jb = sbox[c0 + j];
                            if (iou_gt(jb.x, jb.y, jb.z, jb.w, sarea[c0 + j],
                                       bb.x, bb.y, bb.z, bb.w, ar))
                                sup |= (1u << j);
                        }
                    }
                    s_sup[lane] = sup;
                    unsigned alivem = __ballot_sync(FULL, alive);
                    bool tiny = valid && (bb.z - bb.x >= 1.0f) && (bb.w - bb.y >= 1.0f);
                    unsigned tinym = __ballot_sync(FULL, tiny);
                    __syncwarp();
                    unsigned kept = 0;
#pragma unroll 4
                    for (int i = 0; i < 32; i++) {
                        if ((alivem >> i) & 1u) {
                            if ((s_sup[i] & kept) == 0u) kept |= (1u << i);
                        }
                    }
                    unsigned ktiny = kept & tinym;
                    int cf = __popc(ktiny);
                    if ((ktiny >> lane) & 1u) {
                        int r = found + __popc(ktiny & ((1u << lane) - 1u));
                        if (r < limit) {
                            okx1[r] = bb.x; oky1[r] = bb.y;
                            okx2[r] = bb.z; oky2[r] = bb.w;
                            oksc[r] = sc;
                        }
                    }
                    if (found + cf >= limit) {
                        found = limit;
                        stop = true;
                    } else {
                        found += cf;
                        if ((kept >> lane) & 1u) {
                            int p = nkept + __popc(kept & ((1u << lane) - 1u));
                            if (p < KMAX) { skept[p] = bb; skarea[p] = ar; }
                        }
                        nkept += __popc(kept);
                        if (nkept >= KMAX) stop = true;
                    }
                    __syncwarp();
                }
                if (lane == 0) sh_found = found;
            }
            __syncthreads();
        }

        if (sh_found >= limit || C >= total_valid) break;
    }

    // ---- stage 2: warp-parallel 10-box merge + stable sort + bitmask NMS ----
    if (t < 32) {
        const int cnt = min(sh_found, limit);
        float bx[5];
        bx[0] = bx[1] = bx[2] = bx[3] = 0.f;
        bx[4] = -1.0f;
        if (lane < MAXD) {
            if (lane < cnt) {
                bx[0] = okx1[lane]; bx[1] = oky1[lane];
                bx[2] = okx2[lane]; bx[3] = oky2[lane];
                bx[4] = oksc[lane];
            } else {
#pragma unroll
                for (int c = 0; c < 5; c++) bx[c] = sneg[lane * 5 + c];
            }
            sconf0[lane] = bx[4];
        }
        __syncwarp();
        if (lane < MAXD) {
            int rank = 0;
#pragma unroll
            for (int j = 0; j < MAXD; j++) {
                float cj = sconf0[j];
                rank += (cj > bx[4]) || (cj == bx[4] && j < lane);
            }
#pragma unroll
            for (int c = 0; c < 5; c++) sxb[rank][c] = bx[c];
        }
        __syncwarp();
        if (lane < MAXD) {
#pragma unroll
            for (int c = 0; c < 5; c++) bx[c] = sxb[lane][c];
        }
        __syncwarp();
        unsigned supb = 0;
        if (lane < MAXD) {
            float aA = fmaxf(bx[2] - bx[0], 0.f) * fmaxf(bx[3] - bx[1], 0.f);
#pragma unroll
            for (int j = 0; j < MAXD; j++) {
                float jx1 = sxb[j][0], jy1 = sxb[j][1], jx2 = sxb[j][2], jy2 = sxb[j][3];
                float aJ = fmaxf(jx2 - jx1, 0.f) * fmaxf(jy2 - jy1, 0.f);
                if (iou_gt(jx1, jy1, jx2, jy2, aJ, bx[0], bx[1], bx[2], bx[3], aA))
                    supb |= (1u << j);
            }
            s_supb[lane] = (int)supb;
        }
        unsigned validm = __ballot_sync(FULL, lane < MAXD && bx[4] > 0.0f);
        __syncwarp();
        unsigned kept = 0;
#pragma unroll
        for (int i = 0; i < MAXD; i++) {
            if ((validm >> i) & 1u) {
                if (((unsigned)s_supb[i] & kept & ((1u << i) - 1u)) == 0u)
                    kept |= (1u << i);
            }
        }
        bool kp = (lane < MAXD) && ((kept >> lane) & 1u);
        if (lane < MAXD) {
#pragma unroll
            for (int c = 0; c < 4; c++) {
                out_tb[(size_t)b * MAXD * 4 + lane * 4 + c] = kp ? bx[c] : 0.0f;
                g_ib[b][lane][c] = (int)floorf(bx[c] + 0.5f);
            }
            out_k2[(size_t)b * MAXD + lane] = kp ? 1.0f : 0.0f;
            g_k[b][lane] = kp ? 1 : 0;
        }
    }
    __syncthreads();
    // publish: release flag so this image's render blocks can fix covered pixels
    if (t == 0) {
        __threadfence();
        *(volatile int*)&g_flag[b] = 1;
    }
}

extern "C" void kernel_launch(void* const* d_in, const int* in_sizes, int n_in,
                              void* d_out, int out_size) {
    // inputs: [0]=x (unused), [1]=region_boxes (B,N,5), [2]=neg_boxes (B,10,5)
    const float* region = (const float*)d_in[1];
    const float* neg = (const float*)d_in[2];
    float* out = (float*)d_out;
    float* out_tb = out + (size_t)Bn * Hh * Ww;          // target_boxes segment
    float* out_k2 = out_tb + (size_t)Bn * MAXD * 4;      // keep2 segment

    cudaFuncSetAttribute(fused_kernel, cudaFuncAttributeMaxDynamicSharedMemorySize, SMEM_TOTAL);
    fused_kernel<<<GRID, BDIM, SMEM_TOTAL>>>(region, neg, out, out_tb, out_k2);
}

// round 16
// speedup vs baseline: 1.1189x; 1.0828x over previous
#include <cuda_runtime.h>
#include <cstdint>
#include <climits>
#include <cmath>

#define BDIM 512
constexpr int Bn = 16, Nn = 2000, Hh = 512, Ww = 512, MAXD = 10, TOPK_ = 5;
constexpr float CONF = 0.2f, IOUT = 0.4f;
constexpr int KMAX = 256;
constexpr int FASTC = 128;                 // fast-path candidate cap
constexpr int RPB = 8;                     // render blocks per image
constexpr int RENB = Bn * RPB;             // 128
constexpr int GRID = Bn + RENB;            // 144 <= 148: one wave, all resident
constexpr unsigned FULL = 0xffffffffu;

// NMS -> render handshake (zero-init; reset by last render block each replay)
__device__ int g_flag[Bn];
__device__ int g_ib[Bn][MAXD][4];
__device__ int g_k[Bn][MAXD];
__device__ int g_done;

// IOU > IOUT  <=>  inter*(1+IOUT) > IOUT*(areaA+areaB+1e-9)
__device__ __forceinline__ bool iou_gt(float ax1, float ay1, float ax2, float ay2, float aA,
                                       float bx1, float by1, float bx2, float by2, float aB) {
    float ix1 = fmaxf(ax1, bx1), iy1 = fmaxf(ay1, by1);
    float ix2 = fminf(ax2, bx2), iy2 = fminf(ay2, by2);
    float it = fmaxf(ix2 - ix1, 0.f) * fmaxf(iy2 - iy1, 0.f);
    return it * (1.0f + IOUT) > IOUT * (aA + aB + 1e-9f);
}

extern __shared__ unsigned char dynsmem[];
// layout:
//   sdata : float[10240]   @ 0       (40960 B; staged region slice)
//   ckey  : ULL[2048]      @ 40960   (16384 B)
//   sbox  : float4[2048]   @ 57344   (32768 B)  sorted boxes
//   ssc   : float[2048]    @ 90112   (8192 B)   sorted scores
//   sarea : float[2048]    @ 98304   (8192 B)   sorted areas
constexpr int SMEM_TOTAL = 106496;

__global__ __launch_bounds__(BDIM) void fused_kernel(const float* __restrict__ region,
                                                     const float* __restrict__ neg,
                                                     float* __restrict__ out,
                                                     float* __restrict__ out_tb,
                                                     float* __restrict__ out_k2) {
    const int t = threadIdx.x;
    const int lane = t & 31;

    // ================= render blocks: prefill rows, wait, fix covered =================
    if (blockIdx.x >= Bn) {
        const int rblk = blockIdx.x - Bn;
        const int img = rblk >> 3;
        const int r0 = (rblk & 7) * 64;          // rows [r0, r0+64)
        float* base = out + (size_t)img * Hh * Ww;
        float4* ob = (float4*)base + (size_t)r0 * (Ww / 4);
        float4 one = make_float4(1.f, 1.f, 1.f, 1.f);
#pragma unroll
        for (int i = 0; i < 16; i++) ob[t + i * BDIM] = one;

        __shared__ int sx1[MAXD], sy1[MAXD], sx2[MAXD], sy2[MAXD], sk[MAXD];
        if (t == 0) {
            while (*(volatile int*)&g_flag[img] == 0) { __nanosleep(64); }
            __threadfence();
        }
        __syncthreads();
        if (t < MAXD) {
            sk[t] = g_k[img][t];
            sx1[t] = g_ib[img][t][0]; sy1[t] = g_ib[img][t][1];
            sx2[t] = g_ib[img][t][2]; sy2[t] = g_ib[img][t][3];
        }
        __syncthreads();
        const int wid = t >> 5;
        if (wid < MAXD && sk[wid]) {             // warp per box; boxes <=21px wide
            int x1 = max(sx1[wid], 0), x2 = min(sx2[wid], Ww);
            int y1 = max(max(sy1[wid], r0), 0);
            int y2 = min(min(sy2[wid], r0 + 64), Hh);
            int w = x2 - x1;
            for (int y = y1; y < y2; y++)
                for (int xo = lane; xo < w; xo += 32)
                    base[y * Ww + x1 + xo] = 0.0f;
        }
        __syncthreads();
        if (t == 0) {
            int d = atomicAdd(&g_done, 1);
            if (d == RENB - 1) {
                for (int i = 0; i < Bn; i++) g_flag[i] = 0;
                g_done = 0;
            }
        }
        return;
    }

    // ================= NMS blocks =================
    float* sdata = (float*)dynsmem;
    unsigned long long* ckey = (unsigned long long*)(dynsmem + 40960);
    float4* sbox = (float4*)(dynsmem + 57344);
    float* ssc = (float*)(dynsmem + 90112);
    float* sarea = (float*)(dynsmem + 98304);

    __shared__ float sneg[MAXD * 5];
    __shared__ float okx1[MAXD], oky1[MAXD], okx2[MAXD], oky2[MAXD], oksc[MAXD];
    __shared__ float sxb[MAXD][5];
    __shared__ float4 skept[KMAX];
    __shared__ float skarea[KMAX];
    __shared__ unsigned s_sup[32];
    __shared__ unsigned long long s_supA[FASTC], s_supB[FASTC];
    __shared__ unsigned char s_tf[FASTC];
    __shared__ int okidx[MAXD];
    __shared__ float sconf0[MAXD];
    __shared__ int s_supb[MAXD];
    __shared__ unsigned int sh_maxbits;
    __shared__ int sh_cnt, sh_cntA, sh_found;

    const int b = blockIdx.x;
    const float* rb = region + (size_t)b * Nn * 5;

    if (t == 0) { sh_maxbits = 0u; sh_cntA = 0; }
    __syncthreads();

    // ---- pass 1: coalesced stage of the full 40KB slice + neg ----
    {
        const float4* rb4 = (const float4*)rb;
        float4* s4 = (float4*)sdata;
#pragma unroll
        for (int k = 0; k < 5; k++) {
            int i = t + k * BDIM;
            if (i < Nn * 5 / 4) s4[i] = rb4[i];
        }
        if (t < MAXD * 5) sneg[t] = neg[(size_t)b * MAXD * 5 + t];
    }
    __syncthreads();

    // ---- pass 2: scores from smem -> max + count(sc > CONF) ----
    float rs[4];
    unsigned lm = 0u;
    int myA = 0;
#pragma unroll
    for (int k = 0; k < 4; k++) {
        int j = t + k * BDIM;
        float sc = (j < Nn) ? sdata[j * 5 + 4] : 0.0f;   // scores > 0
        rs[k] = sc;
        lm = max(lm, __float_as_uint(sc));
        myA += (sc > CONF);
    }
#pragma unroll
    for (int off = 16; off; off >>= 1) {
        lm = max(lm, __shfl_xor_sync(FULL, lm, off));
        myA += __shfl_xor_sync(FULL, myA, off);
    }
    if (lane == 0) { atomicMax(&sh_maxbits, lm); atomicAdd(&sh_cntA, myA); }
    __syncthreads();

    const float maxsc = __uint_as_float(sh_maxbits);
    const bool has_conf = maxsc > CONF;
    const float thresh = has_conf ? CONF : 0.0f;
    const int limit = has_conf ? MAXD : TOPK_;
    const int total_valid = has_conf ? sh_cntA : Nn;

    // ---- escalating selection: lev0 = top band (fast), lev1 = all valid (exact) ----
    for (int lev = 0; lev < 2; lev++) {
        if (t == 0) { sh_cnt = 0; sh_found = 0; }
        __syncthreads();
        const float thrL = (lev == 0) ? (maxsc - 0.02f) : -1.0f;
#pragma unroll
        for (int k = 0; k < 4; k++) {
            int j = t + k * BDIM;
            float sc = rs[k];
            if (j < Nn && sc > thresh && sc > thrL) {
                int pos = atomicAdd(&sh_cnt, 1);
                ckey[pos] = ((unsigned long long)__float_as_uint(sc) << 32) |
                            (unsigned)(Nn - 1 - j);
            }
        }
        __syncthreads();
        const int C = sh_cnt;

        // rank sort (keys unique -> exact stable desc order); boxes from smem
        for (int i = t; i < C; i += BDIM) {
            unsigned long long ki = ckey[i];
            int r = 0;
            for (int j = 0; j < C; j++) r += (ckey[j] > ki);
            int js = (Nn - 1) - (int)(unsigned)(ki & 0xffffffffu);
            float x1 = sdata[js * 5 + 0], y1 = sdata[js * 5 + 1];
            float x2 = sdata[js * 5 + 2], y2 = sdata[js * 5 + 3];
            sbox[r] = make_float4(x1, y1, x2, y2);
            sarea[r] = fmaxf(x2 - x1, 0.f) * fmaxf(y2 - y1, 0.f);
            ssc[r] = __uint_as_float((unsigned)(ki >> 32));
        }
        __syncthreads();

        if (C <= FASTC) {
            // ---- FAST PATH: pair-parallel adjacency + serial greedy recurrence ----
            if (t < C) {
                s_supA[t] = 0ull; s_supB[t] = 0ull;
                float4 bb = sbox[t];
                s_tf[t] = ((bb.z - bb.x >= 1.0f) && (bb.w - bb.y >= 1.0f)) ? 1 : 0;
            }
            __syncthreads();
            // distribute the C(C-1)/2 ordered pairs (j < i) across all threads
            const int P = C * (C - 1) / 2;
            for (int p = t; p < P; p += BDIM) {
                int i = (int)((1.0f + sqrtf(1.0f + 8.0f * (float)p)) * 0.5f);
                while (i * (i - 1) / 2 > p) i--;
                while ((i + 1) * i / 2 <= p) i++;
                int j = p - i * (i - 1) / 2;     // j < i
                float4 ib = sbox[i], jb = sbox[j];
                if (iou_gt(jb.x, jb.y, jb.z, jb.w, sarea[j],
                           ib.x, ib.y, ib.z, ib.w, sarea[i])) {
                    if (j < 64) atomicOr(&s_supA[i], 1ull << j);
                    else atomicOr(&s_supB[i], 1ull << (j - 64));
                }
            }
            __syncthreads();
            if (t == 0) {
                unsigned long long keptA = 0ull, keptB = 0ull;
                int f = 0;
                for (int i = 0; i < C && f < limit; i++) {
                    bool sup = ((s_supA[i] & keptA) | (s_supB[i] & keptB)) != 0ull;
                    if (!sup) {
                        if (i < 64) keptA |= 1ull << i; else keptB |= 1ull << (i - 64);
                        if (s_tf[i]) okidx[f++] = i;
                    }
                }
                sh_found = f;
            }
            __syncthreads();
            if (t < sh_found) {            // t < limit <= 10: warp 0
                int r = okidx[t];
                float4 bb = sbox[r];
                okx1[t] = bb.x; oky1[t] = bb.y; okx2[t] = bb.z; oky2[t] = bb.w;
                oksc[t] = ssc[r];
            }
            __syncthreads();
        } else {
            // ---- FALLBACK: chunked single-warp greedy NMS (exact for any C) ----
            if (t < 32) {
                int nkept = 0, found = 0;
                bool stop = false;
                for (int c0 = 0; c0 < C && !stop; c0 += 32) {
                    int ci = c0 + lane;
                    bool valid = ci < C;
                    float4 bb = valid ? sbox[ci] : make_float4(0.f, 0.f, 0.f, 0.f);
                    float ar = valid ? sarea[ci] : 0.f;
                    float sc = valid ? ssc[ci] : 0.f;
                    bool alive = valid;
                    for (int k = 0; k < nkept; k++) {
                        float4 kb = skept[k];
                        if (alive && iou_gt(kb.x, kb.y, kb.z, kb.w, skarea[k],
                                            bb.x, bb.y, bb.z, bb.w, ar))
                            alive = false;
                    }
                    unsigned sup = 0;
#pragma unroll 4
                    for (int j = 0; j < 32; j++) {
                        if (j < lane && valid) {
                            float4 jb = sbox[c0 + j];
                            if (iou_gt(jb.x, jb.y, jb.z, jb.w, sarea[c0 + j],
                                       bb.x, bb.y, bb.z, bb.w, ar))
                                sup |= (1u << j);
                        }
                    }
                    s_sup[lane] = sup;
                    unsigned alivem = __ballot_sync(FULL, alive);
                    bool tiny = valid && (bb.z - bb.x >= 1.0f) && (bb.w - bb.y >= 1.0f);
                    unsigned tinym = __ballot_sync(FULL, tiny);
                    __syncwarp();
                    unsigned kept = 0;
#pragma unroll 4
                    for (int i = 0; i < 32; i++) {
                        if ((alivem >> i) & 1u) {
                            if ((s_sup[i] & kept) == 0u) kept |= (1u << i);
                        }
                    }
                    unsigned ktiny = kept & tinym;
                    int cf = __popc(ktiny);
                    if ((ktiny >> lane) & 1u) {
                        int r = found + __popc(ktiny & ((1u << lane) - 1u));
                        if (r < limit) {
                            okx1[r] = bb.x; oky1[r] = bb.y;
                            okx2[r] = bb.z; oky2[r] = bb.w;
                            oksc[r] = sc;
                        }
                    }
                    if (found + cf >= limit) {
                        found = limit;
                        stop = true;
                    } else {
                        found += cf;
                        if ((kept >> lane) & 1u) {
                            int p = nkept + __popc(kept & ((1u << lane) - 1u));
                            if (p < KMAX) { skept[p] = bb; skarea[p] = ar; }
                        }
                        nkept += __popc(kept);
                        if (nkept >= KMAX) stop = true;
                    }
                    __syncwarp();
                }
                if (lane == 0) sh_found = found;
            }
            __syncthreads();
        }

        if (sh_found >= limit || C >= total_valid) break;
    }

    // ---- stage 2: warp-parallel 10-box merge + stable sort + bitmask NMS ----
    if (t < 32) {
        const int cnt = min(sh_found, limit);
        float bx[5];
        bx[0] = bx[1] = bx[2] = bx[3] = 0.f;
        bx[4] = -1.0f;
        if (lane < MAXD) {
            if (lane < cnt) {
                bx[0] = okx1[lane]; bx[1] = oky1[lane];
                bx[2] = okx2[lane]; bx[3] = oky2[lane];
                bx[4] = oksc[lane];
            } else {
#pragma unroll
                for (int c = 0; c < 5; c++) bx[c] = sneg[lane * 5 + c];
            }
            sconf0[lane] = bx[4];
        }
        __syncwarp();
        if (lane < MAXD) {
            int rank = 0;
#pragma unroll
            for (int j = 0; j < MAXD; j++) {
                float cj = sconf0[j];
                rank += (cj > bx[4]) || (cj == bx[4] && j < lane);
            }
#pragma unroll
            for (int c = 0; c < 5; c++) sxb[rank][c] = bx[c];
        }
        __syncwarp();
        if (lane < MAXD) {
#pragma unroll
            for (int c = 0; c < 5; c++) bx[c] = sxb[lane][c];
        }
        __syncwarp();
        unsigned supb = 0;
        if (lane < MAXD) {
            float aA = fmaxf(bx[2] - bx[0], 0.f) * fmaxf(bx[3] - bx[1], 0.f);
#pragma unroll
            for (int j = 0; j < MAXD; j++) {
                float jx1 = sxb[j][0], jy1 = sxb[j][1], jx2 = sxb[j][2], jy2 = sxb[j][3];
                float aJ = fmaxf(jx2 - jx1, 0.f) * fmaxf(jy2 - jy1, 0.f);
                if (iou_gt(jx1, jy1, jx2, jy2, aJ, bx[0], bx[1], bx[2], bx[3], aA))
                    supb |= (1u << j);
            }
            s_supb[lane] = (int)supb;
        }
        unsigned validm = __ballot_sync(FULL, lane < MAXD && bx[4] > 0.0f);
        __syncwarp();
        unsigned kept = 0;
#pragma unroll
        for (int i = 0; i < MAXD; i++) {
            if ((validm >> i) & 1u) {
                if (((unsigned)s_supb[i] & kept & ((1u << i) - 1u)) == 0u)
                    kept |= (1u << i);
            }
        }
        bool kp = (lane < MAXD) && ((kept >> lane) & 1u);
        if (lane < MAXD) {
#pragma unroll
            for (int c = 0; c < 4; c++) {
                out_tb[(size_t)b * MAXD * 4 + lane * 4 + c] = kp ? bx[c] : 0.0f;
                g_ib[b][lane][c] = (int)floorf(bx[c] + 0.5f);
            }
            out_k2[(size_t)b * MAXD + lane] = kp ? 1.0f : 0.0f;
            g_k[b][lane] = kp ? 1 : 0;
        }
    }
    __syncthreads();
    // publish: release flag so this image's render blocks can fix covered pixels
    if (t == 0) {
        __threadfence();
        *(volatile int*)&g_flag[b] = 1;
    }
}

extern "C" void kernel_launch(void* const* d_in, const int* in_sizes, int n_in,
                              void* d_out, int out_size) {
    // inputs: [0]=x (unused), [1]=region_boxes (B,N,5), [2]=neg_boxes (B,10,5)
    const float* region = (const float*)d_in[1];
    const float* neg = (const float*)d_in[2];
    float* out = (float*)d_out;
    float* out_tb = out + (size_t)Bn * Hh * Ww;          // target_boxes segment
    float* out_k2 = out_tb + (size_t)Bn * MAXD * 4;      // keep2 segment

    cudaFuncSetAttribute(fused_kernel, cudaFuncAttributeMaxDynamicSharedMemorySize, SMEM_TOTAL);
    fused_kernel<<<GRID, BDIM, SMEM_TOTAL>>>(region, neg, out, out_tb, out_k2);
}

// round 17
// speedup vs baseline: 1.3142x; 1.1746x over previous
#include <cuda_runtime.h>
#include <cstdint>
#include <climits>
#include <cmath>

#define BDIM 512
constexpr int Bn = 16, Nn = 2000, Hh = 512, Ww = 512, MAXD = 10, TOPK_ = 5;
constexpr float CONF = 0.2f, IOUT = 0.4f;
constexpr int KMAX = 256;
constexpr int FASTC = 128;                 // fast-path candidate cap
constexpr int RPB = 8;                     // render blocks per image
constexpr int RENB = Bn * RPB;             // 128
constexpr int GRID = Bn + RENB;            // 144 <= 148: one wave, all resident
constexpr unsigned FULL = 0xffffffffu;

// NMS -> render handshake (zero-init; reset by last render block each replay)
__device__ int g_flag[Bn];
__device__ int4 g_pub[Bn][MAXD];           // clipped int box; x2<=x1 => not kept
__device__ int g_done;

// IOU > IOUT  <=>  inter*(1+IOUT) > IOUT*(areaA+areaB+1e-9)
__device__ __forceinline__ bool iou_gt(float ax1, float ay1, float ax2, float ay2, float aA,
                                       float bx1, float by1, float bx2, float by2, float aB) {
    float ix1 = fmaxf(ax1, bx1), iy1 = fmaxf(ay1, by1);
    float ix2 = fminf(ax2, bx2), iy2 = fminf(ay2, by2);
    float it = fmaxf(ix2 - ix1, 0.f) * fmaxf(iy2 - iy1, 0.f);
    return it * (1.0f + IOUT) > IOUT * (aA + aB + 1e-9f);
}

extern __shared__ unsigned char dynsmem[];
// layout:
//   sdata : float[10240]   @ 0       (40960 B; staged region slice)
//   ckey  : ULL[2048]      @ 40960   (16384 B)
//   sbox  : float4[2048]   @ 57344   (32768 B)  sorted boxes
//   ssc   : float[2048]    @ 90112   (8192 B)   sorted scores
//   sarea : float[2048]    @ 98304   (8192 B)   sorted areas
constexpr int SMEM_TOTAL = 106496;

__global__ __launch_bounds__(BDIM) void fused_kernel(const float* __restrict__ region,
                                                     const float* __restrict__ neg,
                                                     float* __restrict__ out,
                                                     float* __restrict__ out_tb,
                                                     float* __restrict__ out_k2) {
    const int t = threadIdx.x;
    const int lane = t & 31;

    // ================= render blocks: prefill rows, wait, fix covered =================
    if (blockIdx.x >= Bn) {
        const int rblk = blockIdx.x - Bn;
        const int img = rblk >> 3;
        const int r0 = (rblk & 7) * 64;          // rows [r0, r0+64)
        float* base = out + (size_t)img * Hh * Ww;
        float4* ob = (float4*)base + (size_t)r0 * (Ww / 4);
        float4 one = make_float4(1.f, 1.f, 1.f, 1.f);
#pragma unroll
        for (int i = 0; i < 16; i++) ob[t + i * BDIM] = one;

        // single spin in thread 0, then barrier; per-warp direct global reads
        if (t == 0) {
            while (*(volatile int*)&g_flag[img] == 0) { __nanosleep(64); }
            __threadfence();
        }
        __syncthreads();
        const int wid = t >> 5;
        if (wid < MAXD) {
            int4 p = *(const int4*)&g_pub[img][wid];     // broadcast LDG.128
            int x1 = p.x, y1 = p.y, x2 = p.z, y2 = p.w;  // already clipped
            if (x2 > x1) {                                // kept
                int ya = max(y1, r0), yb = min(y2, r0 + 64);
                int w = x2 - x1;
                for (int y = ya; y < yb; y++)
                    for (int xo = lane; xo < w; xo += 32)
                        base[y * Ww + x1 + xo] = 0.0f;
            }
        }
        __syncthreads();
        if (t == 0) {
            int d = atomicAdd(&g_done, 1);
            if (d == RENB - 1) {
                for (int i = 0; i < Bn; i++) g_flag[i] = 0;
                g_done = 0;
            }
        }
        return;
    }

    // ================= NMS blocks =================
    float* sdata = (float*)dynsmem;
    unsigned long long* ckey = (unsigned long long*)(dynsmem + 40960);
    float4* sbox = (float4*)(dynsmem + 57344);
    float* ssc = (float*)(dynsmem + 90112);
    float* sarea = (float*)(dynsmem + 98304);

    __shared__ float sneg[MAXD * 5];
    __shared__ float okx1[MAXD], oky1[MAXD], okx2[MAXD], oky2[MAXD], oksc[MAXD];
    __shared__ float sxb[MAXD][5];
    __shared__ float4 skept[KMAX];
    __shared__ float skarea[KMAX];
    __shared__ unsigned s_sup[32];
    __shared__ unsigned long long s_supA[FASTC], s_supB[FASTC];
    __shared__ unsigned char s_tf[FASTC];
    __shared__ int okidx[MAXD];
    __shared__ float sconf0[MAXD];
    __shared__ int s_supb[MAXD];
    __shared__ unsigned int sh_maxbits;
    __shared__ int sh_cnt, sh_cntA, sh_found;

    const int b = blockIdx.x;
    const float* rb = region + (size_t)b * Nn * 5;

    if (t == 0) { sh_maxbits = 0u; sh_cntA = 0; sh_cnt = 0; }
    __syncthreads();

    // ---- pass 1: coalesced stage of the full 40KB slice + neg ----
    {
        const float4* rb4 = (const float4*)rb;
        float4* s4 = (float4*)sdata;
#pragma unroll
        for (int k = 0; k < 5; k++) {
            int i = t + k * BDIM;
            if (i < Nn * 5 / 4) s4[i] = rb4[i];
        }
        if (t < MAXD * 5) sneg[t] = neg[(size_t)b * MAXD * 5 + t];
    }
    __syncthreads();

    // ---- pass 2: scores from smem -> max + count(sc > CONF) ----
    float rs[4];
    unsigned lm = 0u;
    int myA = 0;
#pragma unroll
    for (int k = 0; k < 4; k++) {
        int j = t + k * BDIM;
        float sc = (j < Nn) ? sdata[j * 5 + 4] : 0.0f;   // scores > 0
        rs[k] = sc;
        lm = max(lm, __float_as_uint(sc));
        myA += (sc > CONF);
    }
#pragma unroll
    for (int off = 16; off; off >>= 1) {
        lm = max(lm, __shfl_xor_sync(FULL, lm, off));
        myA += __shfl_xor_sync(FULL, myA, off);
    }
    if (lane == 0) { atomicMax(&sh_maxbits, lm); atomicAdd(&sh_cntA, myA); }
    __syncthreads();

    const float maxsc = __uint_as_float(sh_maxbits);
    const bool has_conf = maxsc > CONF;
    const float thresh = has_conf ? CONF : 0.0f;
    const int limit = has_conf ? MAXD : TOPK_;
    const int total_valid = has_conf ? sh_cntA : Nn;

    // ---- escalating selection: lev0 = top band (fast), lev1 = all valid (exact) ----
    for (int lev = 0; lev < 2; lev++) {
        const float thrL = (lev == 0) ? (maxsc - 0.015f) : -1.0f;
#pragma unroll
        for (int k = 0; k < 4; k++) {
            int j = t + k * BDIM;
            float sc = rs[k];
            if (j < Nn && sc > thresh && sc > thrL) {
                int pos = atomicAdd(&sh_cnt, 1);
                ckey[pos] = ((unsigned long long)__float_as_uint(sc) << 32) |
                            (unsigned)(Nn - 1 - j);
            }
        }
        __syncthreads();
        const int C = sh_cnt;

        // rank sort (keys unique -> exact stable desc order); boxes from smem.
        // Also fold in fast-path mask zeroing + tiny-flag (each rank written once).
        for (int i = t; i < C; i += BDIM) {
            unsigned long long ki = ckey[i];
            int r = 0;
            for (int j = 0; j < C; j++) r += (ckey[j] > ki);
            int js = (Nn - 1) - (int)(unsigned)(ki & 0xffffffffu);
            float x1 = sdata[js * 5 + 0], y1 = sdata[js * 5 + 1];
            float x2 = sdata[js * 5 + 2], y2 = sdata[js * 5 + 3];
            sbox[r] = make_float4(x1, y1, x2, y2);
            sarea[r] = fmaxf(x2 - x1, 0.f) * fmaxf(y2 - y1, 0.f);
            ssc[r] = __uint_as_float((unsigned)(ki >> 32));
            if (r < FASTC) {
                s_supA[r] = 0ull; s_supB[r] = 0ull;
                s_tf[r] = ((x2 - x1 >= 1.0f) && (y2 - y1 >= 1.0f)) ? 1 : 0;
            }
        }
        __syncthreads();

        if (C <= FASTC) {
            // ---- FAST PATH: pair-parallel adjacency + serial greedy recurrence ----
            const int P = C * (C - 1) / 2;
            for (int p = t; p < P; p += BDIM) {
                int i = (int)((1.0f + sqrtf(1.0f + 8.0f * (float)p)) * 0.5f);
                while (i * (i - 1) / 2 > p) i--;
                while ((i + 1) * i / 2 <= p) i++;
                int j = p - i * (i - 1) / 2;     // j < i
                float4 ib = sbox[i], jb = sbox[j];
                if (iou_gt(jb.x, jb.y, jb.z, jb.w, sarea[j],
                           ib.x, ib.y, ib.z, ib.w, sarea[i])) {
                    if (j < 64) atomicOr(&s_supA[i], 1ull << j);
                    else atomicOr(&s_supB[i], 1ull << (j - 64));
                }
            }
            __syncthreads();
            if (t == 0) {
                unsigned long long keptA = 0ull, keptB = 0ull;
                int f = 0;
                for (int i = 0; i < C && f < limit; i++) {
                    bool sup = ((s_supA[i] & keptA) | (s_supB[i] & keptB)) != 0ull;
                    if (!sup) {
                        if (i < 64) keptA |= 1ull << i; else keptB |= 1ull << (i - 64);
                        if (s_tf[i]) okidx[f++] = i;
                    }
                }
                sh_found = f;
            }
            __syncthreads();
            if (t < sh_found) {            // t < limit <= 10: warp 0
                int r = okidx[t];
                float4 bb = sbox[r];
                okx1[t] = bb.x; oky1[t] = bb.y; okx2[t] = bb.z; oky2[t] = bb.w;
                oksc[t] = ssc[r];
            }
            __syncthreads();
        } else {
            // ---- FALLBACK: chunked single-warp greedy NMS (exact for any C) ----
            if (t == 0) sh_found = 0;
            __syncthreads();
            if (t < 32) {
                int nkept = 0, found = 0;
                bool stop = false;
                for (int c0 = 0; c0 < C && !stop; c0 += 32) {
                    int ci = c0 + lane;
                    bool valid = ci < C;
                    float4 bb = valid ? sbox[ci] : make_float4(0.f, 0.f, 0.f, 0.f);
                    float ar = valid ? sarea[ci] : 0.f;
                    float sc = valid ? ssc[ci] : 0.f;
                    bool alive = valid;
                    for (int k = 0; k < nkept; k++) {
                        float4 kb = skept[k];
                        if (alive && iou_gt(kb.x, kb.y, kb.z, kb.w, skarea[k],
                                            bb.x, bb.y, bb.z, bb.w, ar))
                            alive = false;
                    }
                    unsigned sup = 0;
#pragma unroll 4
                    for (int j = 0; j < 32; j++) {
                        if (j < lane && valid) {
                            float4 jb = sbox[c0 + j];
                            if (iou_gt(jb.x, jb.y, jb.z, jb.w, sarea[c0 + j],
                                       bb.x, bb.y, bb.z, bb.w, ar))
                                sup |= (1u << j);
                        }
                    }
                    s_sup[lane] = sup;
                    unsigned alivem = __ballot_sync(FULL, alive);
                    bool tiny = valid && (bb.z - bb.x >= 1.0f) && (bb.w - bb.y >= 1.0f);
                    unsigned tinym = __ballot_sync(FULL, tiny);
                    __syncwarp();
                    unsigned kept = 0;
#pragma unroll 4
                    for (int i = 0; i < 32; i++) {
                        if ((alivem >> i) & 1u) {
                            if ((s_sup[i] & kept) == 0u) kept |= (1u << i);
                        }
                    }
                    unsigned ktiny = kept & tinym;
                    int cf = __popc(ktiny);
                    if ((ktiny >> lane) & 1u) {
                        int r = found + __popc(ktiny & ((1u << lane) - 1u));
                        if (r < limit) {
                            okx1[r] = bb.x; oky1[r] = bb.y;
                            okx2[r] = bb.z; oky2[r] = bb.w;
                            oksc[r] = sc;
                        }
                    }
                    if (found + cf >= limit) {
                        found = limit;
                        stop = true;
                    } else {
                        found += cf;
                        if ((kept >> lane) & 1u) {
                            int p = nkept + __popc(kept & ((1u << lane) - 1u));
                            if (p < KMAX) { skept[p] = bb; skarea[p] = ar; }
                        }
                        nkept += __popc(kept);
                        if (nkept >= KMAX) stop = true;
                    }
                    __syncwarp();
                }
                if (lane == 0) sh_found = found;
            }
            __syncthreads();
        }

        if (sh_found >= limit || C >= total_valid) break;
        if (t == 0) sh_cnt = 0;
        __syncthreads();
    }

    // ---- stage 2: warp-parallel 10-box merge + stable sort + bitmask NMS ----
    if (t < 32) {
        const int cnt = min(sh_found, limit);
        float bx[5];
        bx[0] = bx[1] = bx[2] = bx[3] = 0.f;
        bx[4] = -1.0f;
        if (lane < MAXD) {
            if (lane < cnt) {
                bx[0] = okx1[lane]; bx[1] = oky1[lane];
                bx[2] = okx2[lane]; bx[3] = oky2[lane];
                bx[4] = oksc[lane];
            } else {
#pragma unroll
                for (int c = 0; c < 5; c++) bx[c] = sneg[lane * 5 + c];
            }
            sconf0[lane] = bx[4];
        }
        __syncwarp();
        if (lane < MAXD) {
            int rank = 0;
#pragma unroll
            for (int j = 0; j < MAXD; j++) {
                float cj = sconf0[j];
                rank += (cj > bx[4]) || (cj == bx[4] && j < lane);
            }
#pragma unroll
            for (int c = 0; c < 5; c++) sxb[rank][c] = bx[c];
        }
        __syncwarp();
        if (lane < MAXD) {
#pragma unroll
            for (int c = 0; c < 5; c++) bx[c] = sxb[lane][c];
        }
        __syncwarp();
        unsigned supb = 0;
        if (lane < MAXD) {
            float aA = fmaxf(bx[2] - bx[0], 0.f) * fmaxf(bx[3] - bx[1], 0.f);
#pragma unroll
            for (int j = 0; j < MAXD; j++) {
                float jx1 = sxb[j][0], jy1 = sxb[j][1], jx2 = sxb[j][2], jy2 = sxb[j][3];
                float aJ = fmaxf(jx2 - jx1, 0.f) * fmaxf(jy2 - jy1, 0.f);
                if (iou_gt(jx1, jy1, jx2, jy2, aJ, bx[0], bx[1], bx[2], bx[3], aA))
                    supb |= (1u << j);
            }
            s_supb[lane] = (int)supb;
        }
        unsigned validm = __ballot_sync(FULL, lane < MAXD && bx[4] > 0.0f);
        __syncwarp();
        unsigned kept = 0;
#pragma unroll
        for (int i = 0; i < MAXD; i++) {
            if ((validm >> i) & 1u) {
                if (((unsigned)s_supb[i] & kept & ((1u << i) - 1u)) == 0u)
                    kept |= (1u << i);
            }
        }
        bool kp = (lane < MAXD) && ((kept >> lane) & 1u);
        if (lane < MAXD) {
            int bi[4];
#pragma unroll
            for (int c = 0; c < 4; c++) {
                out_tb[(size_t)b * MAXD * 4 + lane * 4 + c] = kp ? bx[c] : 0.0f;
                bi[c] = (int)floorf(bx[c] + 0.5f);
            }
            out_k2[(size_t)b * MAXD + lane] = kp ? 1.0f : 0.0f;
            // publish clipped int box; sentinel x2<=x1 when not kept/degenerate
            int x1 = max(bi[0], 0), y1 = max(bi[1], 0);
            int x2 = min(bi[2], Ww), y2 = min(bi[3], Hh);
            if (!kp || x2 <= x1 || y2 <= y1) { x1 = 0; x2 = 0; y1 = 0; y2 = 0; }
            g_pub[b][lane] = make_int4(x1, y1, x2, y2);
        }
    }
    __syncthreads();
    // publish: release flag so this image's render blocks can fix covered pixels
    if (t == 0) {
        __threadfence();
        *(volatile int*)&g_flag[b] = 1;
    }
}

extern "C" void kernel_launch(void* const* d_in, const int* in_sizes, int n_in,
                              void* d_out, int out_size) {
    // inputs: [0]=x (unused), [1]=region_boxes (B,N,5), [2]=neg_boxes (B,10,5)
    const float* region = (const float*)d_in[1];
    const float* neg = (const float*)d_in[2];
    float* out = (float*)d_out;
    float* out_tb = out + (size_t)Bn * Hh * Ww;          // target_boxes segment
    float* out_k2 = out_tb + (size_t)Bn * MAXD * 4;      // keep2 segment

    cudaFuncSetAttribute(fused_kernel, cudaFuncAttributeMaxDynamicSharedMemorySize, SMEM_TOTAL);
    fused_kernel<<<GRID, BDIM, SMEM_TOTAL>>>(region, neg, out, out_tb, out_k2);
}